// round 3
// baseline (speedup 1.0000x reference)
#include <cuda_runtime.h>

#define BB 256
#define TT 512
#define EMBD 64
#define HID 128

__device__ float g_pre1[(long)TT * BB * HID];   // [t][b][j], 64 MB
__device__ float g_h2[BB * HID];

// ---------------------------------------------------------------------------
// Kernel 1: pre1[t][b][j] = dot(emb[x[b,t]], Wih1[j]) + b_ih1[j] + b_hh1[j]
// (identical to the 644us R1 version)
// ---------------------------------------------------------------------------
__global__ __launch_bounds__(128) void k_pre1(
    const int* __restrict__ x, const float* __restrict__ emb,
    const float* __restrict__ Wih1, const float* __restrict__ bih1,
    const float* __restrict__ bhh1)
{
    __shared__ __align__(16) float shW[HID * 68];
    __shared__ __align__(16) float4 shE[8 * 16];
    __shared__ int shX[8];

    const int tid = threadIdx.x;   // output feature j

    for (int it = 0; it < 64; ++it) {
        int f = it * 128 + tid;
        int j = f >> 6, k = f & 63;
        shW[j * 68 + k] = Wih1[f];
    }
    __syncthreads();

    float Wr[64];
#pragma unroll
    for (int i = 0; i < 64; ++i) Wr[i] = shW[tid * 68 + i];
    const float bb = bih1[tid] + bhh1[tid];

    const int base = blockIdx.x * 256;              // 256 (b,t) rows per block
    const float4* __restrict__ e4 = (const float4*)emb;

    for (int it = 0; it < 32; ++it) {
        const int rid0 = base + it * 8;             // rid = t*256 + b
        if (tid < 8) {
            int rid = rid0 + tid;
            int t = rid >> 8, b = rid & 255;
            shX[tid] = x[b * TT + t];
        }
        __syncthreads();
        {
            int r = tid >> 4, f = tid & 15;
            shE[r * 16 + f] = e4[(long)shX[r] * 16 + f];
        }
        __syncthreads();

        float acc[8];
#pragma unroll
        for (int r = 0; r < 8; ++r) acc[r] = bb;
#pragma unroll
        for (int k4 = 0; k4 < 16; ++k4) {
#pragma unroll
            for (int r = 0; r < 8; ++r) {
                float4 e = shE[r * 16 + k4];
                acc[r] = fmaf(Wr[4 * k4 + 0], e.x, acc[r]);
                acc[r] = fmaf(Wr[4 * k4 + 1], e.y, acc[r]);
                acc[r] = fmaf(Wr[4 * k4 + 2], e.z, acc[r]);
                acc[r] = fmaf(Wr[4 * k4 + 3], e.w, acc[r]);
            }
        }
#pragma unroll
        for (int r = 0; r < 8; ++r)
            g_pre1[(long)(rid0 + r) * HID + tid] = acc[r];
        __syncthreads();
    }
}

// ---------------------------------------------------------------------------
// Kernel 2: fused two-layer scan, restructured for cross-CTA bubble hiding.
// 256 blocks x 512 threads, 1 batch row per block, 2 blocks co-resident/SM.
// Thread (j = tid&127, p = tid>>7) holds QUARTER-rows (32 floats) of
// W_hh1, W_ih2, W_hh2 => 96 weight regs/thread, fits __launch_bounds__(512,2).
// Per step:
//   A: partial quarter-dots of W_hh1*h1_old and W_hh2*h2_old
//   B: p==0 combines h1_new = tanh(pre + sum); p==1 combines d2 = bb2 + sum
//   C: partial quarter-dots of W_ih2*h1_new
//   D: p==1 combines h2_new = tanh(d2 + sum)
// ---------------------------------------------------------------------------
__global__ __launch_bounds__(512, 2) void k_scan(
    const float* __restrict__ Whh1, const float* __restrict__ Wih2,
    const float* __restrict__ Whh2, const float* __restrict__ bih2,
    const float* __restrict__ bhh2)
{
    __shared__ __align__(16) float sh_h1[HID];
    __shared__ __align__(16) float sh_h2[HID];
    __shared__ __align__(16) float sh_pA[4][HID];
    __shared__ __align__(16) float sh_pB[4][HID];

    const int tid = threadIdx.x;
    const int j = tid & 127;
    const int p = tid >> 7;            // quarter index, uniform per warp
    const int b = blockIdx.x;

    float W1r[32], Wi2r[32], W2r[32];
    {
        const float4* w1 = (const float4*)(Whh1 + j * HID + p * 32);
        const float4* wi = (const float4*)(Wih2 + j * HID + p * 32);
        const float4* w2 = (const float4*)(Whh2 + j * HID + p * 32);
#pragma unroll
        for (int i = 0; i < 8; ++i) {
            float4 a = w1[i];
            W1r[4 * i] = a.x; W1r[4 * i + 1] = a.y; W1r[4 * i + 2] = a.z; W1r[4 * i + 3] = a.w;
            float4 c = wi[i];
            Wi2r[4 * i] = c.x; Wi2r[4 * i + 1] = c.y; Wi2r[4 * i + 2] = c.z; Wi2r[4 * i + 3] = c.w;
            float4 d = w2[i];
            W2r[4 * i] = d.x; W2r[4 * i + 1] = d.y; W2r[4 * i + 2] = d.z; W2r[4 * i + 3] = d.w;
        }
    }

    float bb2 = 0.f;
    if (p == 1) bb2 = bih2[j] + bhh2[j];

    if (tid < HID) { sh_h1[tid] = 0.f; sh_h2[tid] = 0.f; }
    __syncthreads();

    const float* preBase = g_pre1 + (long)b * HID + j;   // [t][b][j]
    float pre_r = 0.f;
    if (p == 0) pre_r = preBase[0];

    const float4* h1q = (const float4*)&sh_h1[p * 32];
    const float4* h2q = (const float4*)&sh_h2[p * 32];
    float d2 = 0.f;

    for (int t = 0; t < TT; ++t) {
        // ---- Phase A: quarter partials of W_hh1*h1_old and W_hh2*h2_old ----
        float a1 = 0.f, a2 = 0.f;
#pragma unroll
        for (int i = 0; i < 8; ++i) {
            float4 h1 = h1q[i];
            a1 = fmaf(W1r[4 * i + 0], h1.x, a1);
            a1 = fmaf(W1r[4 * i + 1], h1.y, a1);
            a1 = fmaf(W1r[4 * i + 2], h1.z, a1);
            a1 = fmaf(W1r[4 * i + 3], h1.w, a1);
            float4 h2 = h2q[i];
            a2 = fmaf(W2r[4 * i + 0], h2.x, a2);
            a2 = fmaf(W2r[4 * i + 1], h2.y, a2);
            a2 = fmaf(W2r[4 * i + 2], h2.z, a2);
            a2 = fmaf(W2r[4 * i + 3], h2.w, a2);
        }
        sh_pA[p][j] = a1;
        sh_pB[p][j] = a2;
        __syncthreads();

        // ---- Phase B ----
        if (p == 0) {
            float v = pre_r + sh_pA[0][j] + sh_pA[1][j] + sh_pA[2][j] + sh_pA[3][j];
            sh_h1[j] = tanhf(v);
            if (t + 1 < TT) pre_r = preBase[(long)(t + 1) * BB * HID];
        } else if (p == 1) {
            d2 = bb2 + sh_pB[0][j] + sh_pB[1][j] + sh_pB[2][j] + sh_pB[3][j];
        }
        __syncthreads();

        // ---- Phase C: quarter partials of W_ih2 * h1_new ----
        float c1 = 0.f;
#pragma unroll
        for (int i = 0; i < 8; ++i) {
            float4 h1 = h1q[i];
            c1 = fmaf(Wi2r[4 * i + 0], h1.x, c1);
            c1 = fmaf(Wi2r[4 * i + 1], h1.y, c1);
            c1 = fmaf(Wi2r[4 * i + 2], h1.z, c1);
            c1 = fmaf(Wi2r[4 * i + 3], h1.w, c1);
        }
        sh_pA[p][j] = c1;
        __syncthreads();

        // ---- Phase D ----
        if (p == 1) {
            float v2 = d2 + sh_pA[0][j] + sh_pA[1][j] + sh_pA[2][j] + sh_pA[3][j];
            sh_h2[j] = tanhf(v2);
        }
        __syncthreads();
    }

    if (tid < HID) g_h2[b * HID + tid] = sh_h2[tid];
}

// ---------------------------------------------------------------------------
// Kernel 3: epilogue — LN -> proj -> tanh -> LN. One block per batch row.
// ---------------------------------------------------------------------------
__global__ __launch_bounds__(128) void k_epi(
    const float* __restrict__ ln_g, const float* __restrict__ ln_b,
    const float* __restrict__ projW, const float* __restrict__ proj_b,
    const float* __restrict__ on_g, const float* __restrict__ on_b,
    float* __restrict__ out)
{
    __shared__ __align__(16) float sh_rep[HID];
    __shared__ float sh_red[8];

    const int j = threadIdx.x;
    const int b = blockIdx.x;

    float v = g_h2[b * HID + j];

    // LN 1
    float s = v, q = v * v;
#pragma unroll
    for (int o = 16; o; o >>= 1) {
        s += __shfl_xor_sync(0xffffffffu, s, o);
        q += __shfl_xor_sync(0xffffffffu, q, o);
    }
    if ((j & 31) == 0) { sh_red[j >> 5] = s; sh_red[4 + (j >> 5)] = q; }
    __syncthreads();
    s = sh_red[0] + sh_red[1] + sh_red[2] + sh_red[3];
    q = sh_red[4] + sh_red[5] + sh_red[6] + sh_red[7];
    float mu = s * (1.f / HID);
    float var = q * (1.f / HID) - mu * mu;
    float rep = (v - mu) * rsqrtf(var + 1e-5f) * ln_g[j] + ln_b[j];
    sh_rep[j] = rep;
    __syncthreads();

    // proj + tanh
    float acc = proj_b[j];
    const float4* w4 = (const float4*)(projW + j * HID);
    const float4* r4 = (const float4*)sh_rep;
#pragma unroll
    for (int i = 0; i < 32; ++i) {
        float4 w = __ldg(&w4[i]);
        float4 r = r4[i];
        acc = fmaf(w.x, r.x, acc);
        acc = fmaf(w.y, r.y, acc);
        acc = fmaf(w.z, r.z, acc);
        acc = fmaf(w.w, r.w, acc);
    }
    float tv = tanhf(acc);

    // LN 2
    __syncthreads();
    s = tv; q = tv * tv;
#pragma unroll
    for (int o = 16; o; o >>= 1) {
        s += __shfl_xor_sync(0xffffffffu, s, o);
        q += __shfl_xor_sync(0xffffffffu, q, o);
    }
    if ((j & 31) == 0) { sh_red[j >> 5] = s; sh_red[4 + (j >> 5)] = q; }
    __syncthreads();
    s = sh_red[0] + sh_red[1] + sh_red[2] + sh_red[3];
    q = sh_red[4] + sh_red[5] + sh_red[6] + sh_red[7];
    float mu2 = s * (1.f / HID);
    float var2 = q * (1.f / HID) - mu2 * mu2;
    out[b * HID + j] = (tv - mu2) * rsqrtf(var2 + 1e-5f) * on_g[j] + on_b[j];
}

// ---------------------------------------------------------------------------
extern "C" void kernel_launch(void* const* d_in, const int* in_sizes, int n_in,
                              void* d_out, int out_size)
{
    const int*   x     = (const int*)  d_in[0];
    const float* emb   = (const float*)d_in[1];
    const float* Wih1  = (const float*)d_in[2];
    const float* bih1  = (const float*)d_in[3];
    const float* Whh1  = (const float*)d_in[4];
    const float* bhh1  = (const float*)d_in[5];
    const float* Wih2  = (const float*)d_in[6];
    const float* bih2  = (const float*)d_in[7];
    const float* Whh2  = (const float*)d_in[8];
    const float* bhh2  = (const float*)d_in[9];
    const float* ln_g  = (const float*)d_in[10];
    const float* ln_b  = (const float*)d_in[11];
    const float* projW = (const float*)d_in[12];
    const float* projb = (const float*)d_in[13];
    const float* on_g  = (const float*)d_in[14];
    const float* on_b  = (const float*)d_in[15];

    k_pre1<<<512, 128>>>(x, emb, Wih1, bih1, bhh1);
    k_scan<<<256, 512>>>(Whh1, Wih2, Whh2, bih2, bhh2);
    k_epi<<<256, 128>>>(ln_g, ln_b, projW, projb, on_g, on_b, (float*)d_out);
}

// round 4
// speedup vs baseline: 3.0415x; 3.0415x over previous
#include <cuda_runtime.h>

#define BB 256
#define TT 512
#define EMBD 64
#define HID 128
#define HPAD 144   // padded row stride (floats) so row0/row1 STS hit disjoint banks

__device__ float g_pre1[(long)TT * BB * HID];   // [t][b][j], 64 MB
__device__ float g_h2[BB * HID];

// ---------------------------------------------------------------------------
// Kernel 1: pre1[t][b][j] = dot(emb[x[b,t]], Wih1[j]) + b_ih1[j] + b_hh1[j]
// (identical to the 644us R1 version)
// ---------------------------------------------------------------------------
__global__ __launch_bounds__(128) void k_pre1(
    const int* __restrict__ x, const float* __restrict__ emb,
    const float* __restrict__ Wih1, const float* __restrict__ bih1,
    const float* __restrict__ bhh1)
{
    __shared__ __align__(16) float shW[HID * 68];
    __shared__ __align__(16) float4 shE[8 * 16];
    __shared__ int shX[8];

    const int tid = threadIdx.x;   // output feature j

    for (int it = 0; it < 64; ++it) {
        int f = it * 128 + tid;
        int j = f >> 6, k = f & 63;
        shW[j * 68 + k] = Wih1[f];
    }
    __syncthreads();

    float Wr[64];
#pragma unroll
    for (int i = 0; i < 64; ++i) Wr[i] = shW[tid * 68 + i];
    const float bb = bih1[tid] + bhh1[tid];

    const int base = blockIdx.x * 256;              // 256 (b,t) rows per block
    const float4* __restrict__ e4 = (const float4*)emb;

    for (int it = 0; it < 32; ++it) {
        const int rid0 = base + it * 8;             // rid = t*256 + b
        if (tid < 8) {
            int rid = rid0 + tid;
            int t = rid >> 8, b = rid & 255;
            shX[tid] = x[b * TT + t];
        }
        __syncthreads();
        {
            int r = tid >> 4, f = tid & 15;
            shE[r * 16 + f] = e4[(long)shX[r] * 16 + f];
        }
        __syncthreads();

        float acc[8];
#pragma unroll
        for (int r = 0; r < 8; ++r) acc[r] = bb;
#pragma unroll
        for (int k4 = 0; k4 < 16; ++k4) {
#pragma unroll
            for (int r = 0; r < 8; ++r) {
                float4 e = shE[r * 16 + k4];
                acc[r] = fmaf(Wr[4 * k4 + 0], e.x, acc[r]);
                acc[r] = fmaf(Wr[4 * k4 + 1], e.y, acc[r]);
                acc[r] = fmaf(Wr[4 * k4 + 2], e.z, acc[r]);
                acc[r] = fmaf(Wr[4 * k4 + 3], e.w, acc[r]);
            }
        }
#pragma unroll
        for (int r = 0; r < 8; ++r)
            g_pre1[(long)(rid0 + r) * HID + tid] = acc[r];
        __syncthreads();
    }
}

// ---------------------------------------------------------------------------
// Kernel 2: fused two-layer scan. 128 blocks x 256 threads, 2 batch rows/block.
// Thread (p = tid&1, j = tid>>1): k-half p of feature j. Partner lane is
// tid^1 (same warp) -> partial sums combine with shfl_xor, no SMEM exchange.
// Double-buffered h1/h2 -> only 2 barriers per step.
// p=1 reads its k-half rotated by 2 float4-chunks (weights loaded permuted to
// match) so paired lanes hit disjoint banks.
// ---------------------------------------------------------------------------
__global__ __launch_bounds__(256, 1) void k_scan(
    const float* __restrict__ Whh1, const float* __restrict__ Wih2,
    const float* __restrict__ Whh2, const float* __restrict__ bih2,
    const float* __restrict__ bhh2)
{
    __shared__ __align__(16) float h1s[2][2][HPAD];   // [buf][row][j]
    __shared__ __align__(16) float h2s[2][2][HPAD];

    const int tid = threadIdx.x;
    const int p = tid & 1;           // k-half, partner in same warp
    const int j = tid >> 1;          // feature 0..127
    const int b0 = blockIdx.x * 2;
    const int rot = 2 * p;           // chunk rotation for bank-conflict-free LDS

    // Load weight quarter-rows permuted by the chunk rotation.
    float W1r[64], Wi2r[64], W2r[64];
    {
        const float4* w1 = (const float4*)(Whh1 + j * HID + p * 64);
        const float4* wi = (const float4*)(Wih2 + j * HID + p * 64);
        const float4* w2 = (const float4*)(Whh2 + j * HID + p * 64);
#pragma unroll
        for (int i = 0; i < 16; ++i) {
            int c = (i + rot) & 15;
            float4 a = w1[c];
            W1r[4 * i] = a.x; W1r[4 * i + 1] = a.y; W1r[4 * i + 2] = a.z; W1r[4 * i + 3] = a.w;
            float4 bq = wi[c];
            Wi2r[4 * i] = bq.x; Wi2r[4 * i + 1] = bq.y; Wi2r[4 * i + 2] = bq.z; Wi2r[4 * i + 3] = bq.w;
            float4 d = w2[c];
            W2r[4 * i] = d.x; W2r[4 * i + 1] = d.y; W2r[4 * i + 2] = d.z; W2r[4 * i + 3] = d.w;
        }
    }
    const float bb2 = bih2[j] + bhh2[j];

    // Zero both buffers (reads at t=0 see zeros).
    for (int i = tid; i < 2 * 2 * HPAD; i += 256) {
        ((float*)h1s)[i] = 0.f;
        ((float*)h2s)[i] = 0.f;
    }
    __syncthreads();

    // pre1 for this thread's own row (row = b0 + p), feature j.
    const float* preBase = g_pre1 + (long)(b0 + p) * HID + j;
    float pre_r = preBase[0];

    for (int t = 0; t < TT; ++t) {
        const int cur = t & 1, nxt = cur ^ 1;

        // ---- Phase A: partials of W_hh1*h1_old (both rows) and W_hh2*h2_old ----
        const float4* h1c0 = (const float4*)&h1s[cur][0][p * 64];
        const float4* h1c1 = (const float4*)&h1s[cur][1][p * 64];
        const float4* h2c0 = (const float4*)&h2s[cur][0][p * 64];
        const float4* h2c1 = (const float4*)&h2s[cur][1][p * 64];

        float a0 = 0.f, a1 = 0.f, e0 = 0.f, e1 = 0.f;
#pragma unroll
        for (int i = 0; i < 16; ++i) {
            int c = (i + rot) & 15;
            float4 u = h1c0[c];
            a0 = fmaf(W1r[4 * i + 0], u.x, a0);
            a0 = fmaf(W1r[4 * i + 1], u.y, a0);
            a0 = fmaf(W1r[4 * i + 2], u.z, a0);
            a0 = fmaf(W1r[4 * i + 3], u.w, a0);
            float4 v = h1c1[c];
            a1 = fmaf(W1r[4 * i + 0], v.x, a1);
            a1 = fmaf(W1r[4 * i + 1], v.y, a1);
            a1 = fmaf(W1r[4 * i + 2], v.z, a1);
            a1 = fmaf(W1r[4 * i + 3], v.w, a1);
            float4 g0 = h2c0[c];
            e0 = fmaf(W2r[4 * i + 0], g0.x, e0);
            e0 = fmaf(W2r[4 * i + 1], g0.y, e0);
            e0 = fmaf(W2r[4 * i + 2], g0.z, e0);
            e0 = fmaf(W2r[4 * i + 3], g0.w, e0);
            float4 g1 = h2c1[c];
            e1 = fmaf(W2r[4 * i + 0], g1.x, e1);
            e1 = fmaf(W2r[4 * i + 1], g1.y, e1);
            e1 = fmaf(W2r[4 * i + 2], g1.z, e1);
            e1 = fmaf(W2r[4 * i + 3], g1.w, e1);
        }
        // Combine halves with the partner lane.
        float fa0 = a0 + __shfl_xor_sync(0xffffffffu, a0, 1);
        float fa1 = a1 + __shfl_xor_sync(0xffffffffu, a1, 1);
        float fe0 = e0 + __shfl_xor_sync(0xffffffffu, e0, 1);
        float fe1 = e1 + __shfl_xor_sync(0xffffffffu, e1, 1);

        float h1n = tanhf(pre_r + (p ? fa1 : fa0));   // own row's new h1
        float d2  = bb2 + (p ? fe1 : fe0);            // own row's h2 pre-act (partial)
        if (t + 1 < TT) pre_r = preBase[(long)(t + 1) * BB * HID];

        h1s[nxt][p][j] = h1n;
        __syncthreads();

        // ---- Phase B: partials of W_ih2 * h1_new (both rows) ----
        const float4* n0 = (const float4*)&h1s[nxt][0][p * 64];
        const float4* n1 = (const float4*)&h1s[nxt][1][p * 64];
        float c0 = 0.f, c1 = 0.f;
#pragma unroll
        for (int i = 0; i < 16; ++i) {
            int c = (i + rot) & 15;
            float4 u = n0[c];
            c0 = fmaf(Wi2r[4 * i + 0], u.x, c0);
            c0 = fmaf(Wi2r[4 * i + 1], u.y, c0);
            c0 = fmaf(Wi2r[4 * i + 2], u.z, c0);
            c0 = fmaf(Wi2r[4 * i + 3], u.w, c0);
            float4 v = n1[c];
            c1 = fmaf(Wi2r[4 * i + 0], v.x, c1);
            c1 = fmaf(Wi2r[4 * i + 1], v.y, c1);
            c1 = fmaf(Wi2r[4 * i + 2], v.z, c1);
            c1 = fmaf(Wi2r[4 * i + 3], v.w, c1);
        }
        float fc0 = c0 + __shfl_xor_sync(0xffffffffu, c0, 1);
        float fc1 = c1 + __shfl_xor_sync(0xffffffffu, c1, 1);

        float h2n = tanhf(d2 + (p ? fc1 : fc0));
        h2s[nxt][p][j] = h2n;
        __syncthreads();
    }

    // After t=511 (odd), last write was to buffer nxt = 0.
    g_h2[(b0 + p) * HID + j] = h2s[0][p][j];
}

// ---------------------------------------------------------------------------
// Kernel 3: epilogue — LN -> proj -> tanh -> LN. One block per batch row.
// ---------------------------------------------------------------------------
__global__ __launch_bounds__(128) void k_epi(
    const float* __restrict__ ln_g, const float* __restrict__ ln_b,
    const float* __restrict__ projW, const float* __restrict__ proj_b,
    const float* __restrict__ on_g, const float* __restrict__ on_b,
    float* __restrict__ out)
{
    __shared__ __align__(16) float sh_rep[HID];
    __shared__ float sh_red[8];

    const int j = threadIdx.x;
    const int b = blockIdx.x;

    float v = g_h2[b * HID + j];

    // LN 1
    float s = v, q = v * v;
#pragma unroll
    for (int o = 16; o; o >>= 1) {
        s += __shfl_xor_sync(0xffffffffu, s, o);
        q += __shfl_xor_sync(0xffffffffu, q, o);
    }
    if ((j & 31) == 0) { sh_red[j >> 5] = s; sh_red[4 + (j >> 5)] = q; }
    __syncthreads();
    s = sh_red[0] + sh_red[1] + sh_red[2] + sh_red[3];
    q = sh_red[4] + sh_red[5] + sh_red[6] + sh_red[7];
    float mu = s * (1.f / HID);
    float var = q * (1.f / HID) - mu * mu;
    float rep = (v - mu) * rsqrtf(var + 1e-5f) * ln_g[j] + ln_b[j];
    sh_rep[j] = rep;
    __syncthreads();

    // proj + tanh
    float acc = proj_b[j];
    const float4* w4 = (const float4*)(projW + j * HID);
    const float4* r4 = (const float4*)sh_rep;
#pragma unroll
    for (int i = 0; i < 32; ++i) {
        float4 w = __ldg(&w4[i]);
        float4 r = r4[i];
        acc = fmaf(w.x, r.x, acc);
        acc = fmaf(w.y, r.y, acc);
        acc = fmaf(w.z, r.z, acc);
        acc = fmaf(w.w, r.w, acc);
    }
    float tv = tanhf(acc);

    // LN 2
    __syncthreads();
    s = tv; q = tv * tv;
#pragma unroll
    for (int o = 16; o; o >>= 1) {
        s += __shfl_xor_sync(0xffffffffu, s, o);
        q += __shfl_xor_sync(0xffffffffu, q, o);
    }
    if ((j & 31) == 0) { sh_red[j >> 5] = s; sh_red[4 + (j >> 5)] = q; }
    __syncthreads();
    s = sh_red[0] + sh_red[1] + sh_red[2] + sh_red[3];
    q = sh_red[4] + sh_red[5] + sh_red[6] + sh_red[7];
    float mu2 = s * (1.f / HID);
    float var2 = q * (1.f / HID) - mu2 * mu2;
    out[b * HID + j] = (tv - mu2) * rsqrtf(var2 + 1e-5f) * on_g[j] + on_b[j];
}

// ---------------------------------------------------------------------------
extern "C" void kernel_launch(void* const* d_in, const int* in_sizes, int n_in,
                              void* d_out, int out_size)
{
    const int*   x     = (const int*)  d_in[0];
    const float* emb   = (const float*)d_in[1];
    const float* Wih1  = (const float*)d_in[2];
    const float* bih1  = (const float*)d_in[3];
    const float* Whh1  = (const float*)d_in[4];
    const float* bhh1  = (const float*)d_in[5];
    const float* Wih2  = (const float*)d_in[6];
    const float* bih2  = (const float*)d_in[7];
    const float* Whh2  = (const float*)d_in[8];
    const float* bhh2  = (const float*)d_in[9];
    const float* ln_g  = (const float*)d_in[10];
    const float* ln_b  = (const float*)d_in[11];
    const float* projW = (const float*)d_in[12];
    const float* projb = (const float*)d_in[13];
    const float* on_g  = (const float*)d_in[14];
    const float* on_b  = (const float*)d_in[15];

    k_pre1<<<512, 128>>>(x, emb, Wih1, bih1, bhh1);
    k_scan<<<128, 256>>>(Whh1, Wih2, Whh2, bih2, bhh2);
    k_epi<<<256, 128>>>(ln_g, ln_b, projW, projb, on_g, on_b, (float*)d_out);
}